// round 4
// baseline (speedup 1.0000x reference)
#include <cuda_runtime.h>

// MPS forward, "row-lane" design.
// y_{n+1}[b] = act( sum_{a,i} y_n[a] * A[c,site,a,i,b] * x[batch,i,site] )
// BATCH=1024, CHANNEL=10, LENGTH=784, CHI=64, D=2.
//
// One WARP owns one chain: (channel c, 16 batches). 640 single-warp blocks ->
// ~4.3 warps/SM, all resident in one wave. No shared-memory A: lane l owns the
// quad A[a, i=l>>4, 4*(l&15) .. +3]; one LDG.128 per a-row is 512B of fully
// distinct, coalesced data (L2-cached, 64 warps/channel reuse). y lives in 8KB
// smem per warp and is read only via all-lane-broadcast LDS.128 (conflict-free).

namespace {
constexpr int LEN  = 784;
constexpr int NCH  = 10;
constexpr int BTCH = 1024;
constexpr int TB   = 16;              // batches per warp/chain
constexpr int SITE_F = 8192;          // floats per (channel,site) tensor
}

__device__ float g_xT[2 * LEN * BTCH];   // x transposed: [i][site][batch]

__global__ void xpose_kernel(const float* __restrict__ x)
{
    int idx = blockIdx.x * blockDim.x + threadIdx.x;   // linear over output
    if (idx >= 2 * LEN * BTCH) return;
    int b    = idx & (BTCH - 1);
    int t    = idx >> 10;           // i*LEN + site
    int i    = t / LEN;
    int site = t - i * LEN;
    g_xT[idx] = x[(size_t)b * (2 * LEN) + i * LEN + site];
}

__device__ __forceinline__ float act_sig(float v) {
    // (tanh(v)+1)/2 == sigmoid(2v)
    return __fdividef(1.0f, 1.0f + __expf(-2.0f * v));
}

__device__ __forceinline__ float4 ldg4(const float* p) {
    return __ldg(reinterpret_cast<const float4*>(p));
}

__global__ void __launch_bounds__(32)
mps_main(const float* __restrict__ tens, float* __restrict__ out)
{
    __shared__ float ys[2][TB][64];      // ping-pong carried state, 8KB

    const int lane = threadIdx.x;
    const int bid  = blockIdx.x;
    const int c    = bid % NCH;
    const int b0   = (bid / NCH) * TB;
    const int li   = lane & 15;          // column-quad index (cols 4li..4li+3)
    const int ihalf = lane >> 4;         // 0: i=0 quads, 1: i=1 quads

    // init y (input of site 0): y[bt][a] = (a==0)
    for (int k = lane; k < TB * 64; k += 32)
        (&ys[0][0][0])[k] = 0.f;
    __syncwarp();
    if (lane < TB) ys[0][lane][0] = 1.0f;
    __syncwarp();

    // lane's quad base inside each 128-float a-row: offset 4*lane floats
    const float* Tq = tens + (size_t)c * LEN * SITE_F + lane * 4;

    float4 Abuf0[4], Abuf1[4];           // double-buffered a-row quads
    #pragma unroll
    for (int j = 0; j < 4; ++j)
        Abuf1[j] = ldg4(Tq + j * 128);   // site 0, rows 0..3

    int p = 0;
    for (int site = 0; site < LEN; ++site) {
        const float* Ts = Tq + (size_t)site * SITE_F;
        // this lane's x value for the site (i = ihalf, batch = b0+li)
        const float xreg = g_xT[ihalf * (LEN * BTCH) + site * BTCH + b0 + li];

        float4 acc[TB];
        #pragma unroll
        for (int bt = 0; bt < TB; ++bt)
            acc[bt] = make_float4(0.f, 0.f, 0.f, 0.f);

        const float (*yp)[64] = ys[p];

        #pragma unroll 2
        for (int a2 = 0; a2 < 8; ++a2) {
            // phase A: prefetch rows 8*a2+4, consume Abuf1 (rows 8*a2)
            {
                const float* rp = Ts + (8 * a2 + 4) * 128;
                #pragma unroll
                for (int j = 0; j < 4; ++j) Abuf0[j] = ldg4(rp + j * 128);
            }
            {
                const int a4 = 2 * a2;
                #pragma unroll
                for (int bt = 0; bt < TB; ++bt) {
                    const float4 y4 = *reinterpret_cast<const float4*>(&yp[bt][4 * a4]);
                    acc[bt].x = fmaf(y4.x, Abuf1[0].x, acc[bt].x);
                    acc[bt].y = fmaf(y4.x, Abuf1[0].y, acc[bt].y);
                    acc[bt].z = fmaf(y4.x, Abuf1[0].z, acc[bt].z);
                    acc[bt].w = fmaf(y4.x, Abuf1[0].w, acc[bt].w);
                    acc[bt].x = fmaf(y4.y, Abuf1[1].x, acc[bt].x);
                    acc[bt].y = fmaf(y4.y, Abuf1[1].y, acc[bt].y);
                    acc[bt].z = fmaf(y4.y, Abuf1[1].z, acc[bt].z);
                    acc[bt].w = fmaf(y4.y, Abuf1[1].w, acc[bt].w);
                    acc[bt].x = fmaf(y4.z, Abuf1[2].x, acc[bt].x);
                    acc[bt].y = fmaf(y4.z, Abuf1[2].y, acc[bt].y);
                    acc[bt].z = fmaf(y4.z, Abuf1[2].z, acc[bt].z);
                    acc[bt].w = fmaf(y4.z, Abuf1[2].w, acc[bt].w);
                    acc[bt].x = fmaf(y4.w, Abuf1[3].x, acc[bt].x);
                    acc[bt].y = fmaf(y4.w, Abuf1[3].y, acc[bt].y);
                    acc[bt].z = fmaf(y4.w, Abuf1[3].z, acc[bt].z);
                    acc[bt].w = fmaf(y4.w, Abuf1[3].w, acc[bt].w);
                }
            }
            // phase B: prefetch rows 8*a2+8 (or next site rows 0..3), consume Abuf0
            {
                const float* rp = (a2 < 7) ? (Ts + (8 * a2 + 8) * 128)
                                           : ((site < LEN - 1) ? (Ts + SITE_F) : Ts);
                #pragma unroll
                for (int j = 0; j < 4; ++j) Abuf1[j] = ldg4(rp + j * 128);
            }
            {
                const int a4 = 2 * a2 + 1;
                #pragma unroll
                for (int bt = 0; bt < TB; ++bt) {
                    const float4 y4 = *reinterpret_cast<const float4*>(&yp[bt][4 * a4]);
                    acc[bt].x = fmaf(y4.x, Abuf0[0].x, acc[bt].x);
                    acc[bt].y = fmaf(y4.x, Abuf0[0].y, acc[bt].y);
                    acc[bt].z = fmaf(y4.x, Abuf0[0].z, acc[bt].z);
                    acc[bt].w = fmaf(y4.x, Abuf0[0].w, acc[bt].w);
                    acc[bt].x = fmaf(y4.y, Abuf0[1].x, acc[bt].x);
                    acc[bt].y = fmaf(y4.y, Abuf0[1].y, acc[bt].y);
                    acc[bt].z = fmaf(y4.y, Abuf0[1].z, acc[bt].z);
                    acc[bt].w = fmaf(y4.y, Abuf0[1].w, acc[bt].w);
                    acc[bt].x = fmaf(y4.z, Abuf0[2].x, acc[bt].x);
                    acc[bt].y = fmaf(y4.z, Abuf0[2].y, acc[bt].y);
                    acc[bt].z = fmaf(y4.z, Abuf0[2].z, acc[bt].z);
                    acc[bt].w = fmaf(y4.z, Abuf0[2].w, acc[bt].w);
                    acc[bt].x = fmaf(y4.w, Abuf0[3].x, acc[bt].x);
                    acc[bt].y = fmaf(y4.w, Abuf0[3].y, acc[bt].y);
                    acc[bt].z = fmaf(y4.w, Abuf0[3].z, acc[bt].z);
                    acc[bt].w = fmaf(y4.w, Abuf0[3].w, acc[bt].w);
                }
            }
        }

        if (site == LEN - 1) {
            // last site: no activation; only column 0 survives (dims[784]==1)
            #pragma unroll 1
            for (int bt = 0; bt < TB; ++bt) {
                const float z1  = __shfl_xor_sync(0xffffffffu, acc[bt].x, 16);
                const float xv0 = __shfl_sync(0xffffffffu, xreg, bt);
                const float xv1 = __shfl_sync(0xffffffffu, xreg, 16 + bt);
                if (lane == 0)
                    out[(size_t)(b0 + bt) * NCH + c] = fmaf(xv0, acc[bt].x, xv1 * z1);
            }
        } else {
            // bond dimension of this site's output
            const int nn = site + 1;
            const int up = (nn >= 6) ? 64 : (1 << nn);
            const int dn = ((LEN - nn) >= 6) ? 64 : (1 << (LEN - nn));
            const int dnext = (up < dn) ? up : dn;
            const int cb = 4 * li;

            #pragma unroll 4
            for (int bt = 0; bt < TB; ++bt) {
                float4 zo;
                zo.x = __shfl_xor_sync(0xffffffffu, acc[bt].x, 16);
                zo.y = __shfl_xor_sync(0xffffffffu, acc[bt].y, 16);
                zo.z = __shfl_xor_sync(0xffffffffu, acc[bt].z, 16);
                zo.w = __shfl_xor_sync(0xffffffffu, acc[bt].w, 16);
                const float xv0 = __shfl_sync(0xffffffffu, xreg, bt);
                const float xv1 = __shfl_sync(0xffffffffu, xreg, 16 + bt);
                if (lane < 16) {
                    float4 v;
                    v.x = fmaf(xv0, acc[bt].x, xv1 * zo.x);
                    v.y = fmaf(xv0, acc[bt].y, xv1 * zo.y);
                    v.z = fmaf(xv0, acc[bt].z, xv1 * zo.z);
                    v.w = fmaf(xv0, acc[bt].w, xv1 * zo.w);
                    float4 o;
                    o.x = (cb + 0 < dnext) ? act_sig(v.x) : 0.f;
                    o.y = (cb + 1 < dnext) ? act_sig(v.y) : 0.f;
                    o.z = (cb + 2 < dnext) ? act_sig(v.z) : 0.f;
                    o.w = (cb + 3 < dnext) ? act_sig(v.w) : 0.f;
                    *reinterpret_cast<float4*>(&ys[1 - p][bt][cb]) = o;
                }
            }
            __syncwarp();
            p ^= 1;
        }
    }
}

extern "C" void kernel_launch(void* const* d_in, const int* in_sizes, int n_in,
                              void* d_out, int out_size)
{
    const float* a0 = (const float*)d_in[0];
    const float* a1 = (const float*)d_in[1];
    // x: 1024*2*784 = 1,605,632 ; tensors: 10*784*64*2*64 = 64,225,280
    const float* x = a0;
    const float* t = a1;
    if (n_in >= 2 && in_sizes[0] > in_sizes[1]) { x = a1; t = a0; }

    const int nx = 2 * LEN * BTCH;
    xpose_kernel<<<(nx + 255) / 256, 256>>>(x);

    const int blocks = NCH * (BTCH / TB);   // 640 single-warp blocks
    mps_main<<<blocks, 32>>>(t, (float*)d_out);
}

// round 5
// speedup vs baseline: 1.3892x; 1.3892x over previous
#include <cuda_runtime.h>

// MPS forward, row-lane design v2: 4 warps/CTA for latency hiding.
// y_{n+1}[b] = act( sum_{a,i} y_n[a] * A[c,site,a,i,b] * x[batch,i,site] )
// BATCH=1024, CHANNEL=10, LENGTH=784, CHI=64, D=2.
//
// CTA = (channel, 16 batches), 4 warps x 4 batches. Lane l owns the quad
// A[a, i=l>>4, 4*(l&15)..+3]; each LDG.128 is 512B coalesced. The 4 warps
// stream the SAME A addresses, phase-locked by one __syncthreads per site,
// so L1 serves the intra-CTA reuse and L2 sees ~one stream per CTA.
// y lives in smem, read via all-lane-broadcast LDS.128 (conflict-free).

namespace {
constexpr int LEN    = 784;
constexpr int NCH    = 10;
constexpr int BTCH   = 1024;
constexpr int TB     = 4;            // batches per warp
constexpr int NW     = 4;            // warps per CTA
constexpr int NT     = NW * 32;      // 128 threads
constexpr int SITE_F = 8192;         // floats per (channel,site) tensor
}

__device__ float g_xT[2 * LEN * BTCH];   // x transposed: [i][site][batch]

__global__ void xpose_kernel(const float* __restrict__ x)
{
    int idx = blockIdx.x * blockDim.x + threadIdx.x;
    if (idx >= 2 * LEN * BTCH) return;
    int b    = idx & (BTCH - 1);
    int t    = idx >> 10;            // i*LEN + site
    int i    = t / LEN;
    int site = t - i * LEN;
    g_xT[idx] = x[(size_t)b * (2 * LEN) + i * LEN + site];
}

__device__ __forceinline__ float act_sig(float v) {
    // (tanh(v)+1)/2 == sigmoid(2v)
    return __fdividef(1.0f, 1.0f + __expf(-2.0f * v));
}

__device__ __forceinline__ float4 ldg4(const float* p) {
    return __ldg(reinterpret_cast<const float4*>(p));
}

__global__ void __launch_bounds__(NT)
mps_main(const float* __restrict__ tens, float* __restrict__ out)
{
    __shared__ float ys[2][NW][TB][64];   // ping-pong carried state, 8KB

    const int lane = threadIdx.x & 31;
    const int w    = threadIdx.x >> 5;
    const int bid  = blockIdx.x;
    const int c    = bid % NCH;
    const int B0   = (bid / NCH) * (NW * TB);   // CTA batch base
    const int bb   = B0 + w * TB;               // warp batch base
    const int li   = lane & 15;                 // column quad (cols 4li..4li+3)

    // init y (input of site 0): y[bt][a] = (a==0)
    for (int k = lane; k < TB * 64; k += 32)
        (&ys[0][w][0][0])[k] = ((k & 63) == 0) ? 1.0f : 0.0f;
    __syncthreads();

    // lane's quad offset inside each 128-float a-row = 4*lane
    const float* Tq = tens + (size_t)c * LEN * SITE_F + lane * 4;

    float4 Abuf0[4], Abuf1[4];
    #pragma unroll
    for (int j = 0; j < 4; ++j)
        Abuf1[j] = ldg4(Tq + j * 128);   // site 0, rows 0..3

    int p = 0;
    for (int site = 0; site < LEN; ++site) {
        __syncthreads();   // phase-lock warps -> intra-CTA A reuse hits L1

        const float* Ts = Tq + (size_t)site * SITE_F;

        // x staging: lane<8 holds x[i=lane>>2][site][bb + (lane&3)]
        float xl = 0.f;
        if (lane < 8)
            xl = g_xT[(lane >> 2) * (LEN * BTCH) + site * BTCH + bb + (lane & 3)];

        float4 acc[TB];
        #pragma unroll
        for (int bt = 0; bt < TB; ++bt)
            acc[bt] = make_float4(0.f, 0.f, 0.f, 0.f);

        const float (*yp)[64] = ys[p][w];

        #pragma unroll 2
        for (int a2 = 0; a2 < 8; ++a2) {
            // phase A: prefetch rows 8*a2+4, consume Abuf1 (rows 8*a2..+3)
            {
                const float* rp = Ts + (8 * a2 + 4) * 128;
                #pragma unroll
                for (int j = 0; j < 4; ++j) Abuf0[j] = ldg4(rp + j * 128);
            }
            {
                const int a4 = 2 * a2;
                #pragma unroll
                for (int bt = 0; bt < TB; ++bt) {
                    const float4 y4 = *reinterpret_cast<const float4*>(&yp[bt][4 * a4]);
                    acc[bt].x = fmaf(y4.x, Abuf1[0].x, acc[bt].x);
                    acc[bt].y = fmaf(y4.x, Abuf1[0].y, acc[bt].y);
                    acc[bt].z = fmaf(y4.x, Abuf1[0].z, acc[bt].z);
                    acc[bt].w = fmaf(y4.x, Abuf1[0].w, acc[bt].w);
                    acc[bt].x = fmaf(y4.y, Abuf1[1].x, acc[bt].x);
                    acc[bt].y = fmaf(y4.y, Abuf1[1].y, acc[bt].y);
                    acc[bt].z = fmaf(y4.y, Abuf1[1].z, acc[bt].z);
                    acc[bt].w = fmaf(y4.y, Abuf1[1].w, acc[bt].w);
                    acc[bt].x = fmaf(y4.z, Abuf1[2].x, acc[bt].x);
                    acc[bt].y = fmaf(y4.z, Abuf1[2].y, acc[bt].y);
                    acc[bt].z = fmaf(y4.z, Abuf1[2].z, acc[bt].z);
                    acc[bt].w = fmaf(y4.z, Abuf1[2].w, acc[bt].w);
                    acc[bt].x = fmaf(y4.w, Abuf1[3].x, acc[bt].x);
                    acc[bt].y = fmaf(y4.w, Abuf1[3].y, acc[bt].y);
                    acc[bt].z = fmaf(y4.w, Abuf1[3].z, acc[bt].z);
                    acc[bt].w = fmaf(y4.w, Abuf1[3].w, acc[bt].w);
                }
            }
            // phase B: prefetch rows 8*a2+8 (or next site rows 0..3), consume Abuf0
            {
                const float* rp = (a2 < 7) ? (Ts + (8 * a2 + 8) * 128)
                                           : ((site < LEN - 1) ? (Ts + SITE_F) : Ts);
                #pragma unroll
                for (int j = 0; j < 4; ++j) Abuf1[j] = ldg4(rp + j * 128);
            }
            {
                const int a4 = 2 * a2 + 1;
                #pragma unroll
                for (int bt = 0; bt < TB; ++bt) {
                    const float4 y4 = *reinterpret_cast<const float4*>(&yp[bt][4 * a4]);
                    acc[bt].x = fmaf(y4.x, Abuf0[0].x, acc[bt].x);
                    acc[bt].y = fmaf(y4.x, Abuf0[0].y, acc[bt].y);
                    acc[bt].z = fmaf(y4.x, Abuf0[0].z, acc[bt].z);
                    acc[bt].w = fmaf(y4.x, Abuf0[0].w, acc[bt].w);
                    acc[bt].x = fmaf(y4.y, Abuf0[1].x, acc[bt].x);
                    acc[bt].y = fmaf(y4.y, Abuf0[1].y, acc[bt].y);
                    acc[bt].z = fmaf(y4.y, Abuf0[1].z, acc[bt].z);
                    acc[bt].w = fmaf(y4.y, Abuf0[1].w, acc[bt].w);
                    acc[bt].x = fmaf(y4.z, Abuf0[2].x, acc[bt].x);
                    acc[bt].y = fmaf(y4.z, Abuf0[2].y, acc[bt].y);
                    acc[bt].z = fmaf(y4.z, Abuf0[2].z, acc[bt].z);
                    acc[bt].w = fmaf(y4.z, Abuf0[2].w, acc[bt].w);
                    acc[bt].x = fmaf(y4.w, Abuf0[3].x, acc[bt].x);
                    acc[bt].y = fmaf(y4.w, Abuf0[3].y, acc[bt].y);
                    acc[bt].z = fmaf(y4.w, Abuf0[3].z, acc[bt].z);
                    acc[bt].w = fmaf(y4.w, Abuf0[3].w, acc[bt].w);
                }
            }
        }

        if (site == LEN - 1) {
            // last site: no activation; only column 0 survives (dims[784]==1)
            #pragma unroll
            for (int bt = 0; bt < TB; ++bt) {
                const float z1  = __shfl_xor_sync(0xffffffffu, acc[bt].x, 16);
                const float xv0 = __shfl_sync(0xffffffffu, xl, bt);
                const float xv1 = __shfl_sync(0xffffffffu, xl, 4 + bt);
                if (lane == 0)
                    out[(size_t)(bb + bt) * NCH + c] = fmaf(xv0, acc[bt].x, xv1 * z1);
            }
        } else {
            // bond dimension of this site's output
            const int nn = site + 1;
            const int up = (nn >= 6) ? 64 : (1 << nn);
            const int dn = ((LEN - nn) >= 6) ? 64 : (1 << (LEN - nn));
            const int dnext = (up < dn) ? up : dn;
            const int cb = 4 * li;

            #pragma unroll
            for (int bt = 0; bt < TB; ++bt) {
                float4 zo;
                zo.x = __shfl_xor_sync(0xffffffffu, acc[bt].x, 16);
                zo.y = __shfl_xor_sync(0xffffffffu, acc[bt].y, 16);
                zo.z = __shfl_xor_sync(0xffffffffu, acc[bt].z, 16);
                zo.w = __shfl_xor_sync(0xffffffffu, acc[bt].w, 16);
                const float xv0 = __shfl_sync(0xffffffffu, xl, bt);
                const float xv1 = __shfl_sync(0xffffffffu, xl, 4 + bt);
                if (lane < 16) {
                    float4 v;
                    v.x = fmaf(xv0, acc[bt].x, xv1 * zo.x);
                    v.y = fmaf(xv0, acc[bt].y, xv1 * zo.y);
                    v.z = fmaf(xv0, acc[bt].z, xv1 * zo.z);
                    v.w = fmaf(xv0, acc[bt].w, xv1 * zo.w);
                    float4 o;
                    o.x = (cb + 0 < dnext) ? act_sig(v.x) : 0.f;
                    o.y = (cb + 1 < dnext) ? act_sig(v.y) : 0.f;
                    o.z = (cb + 2 < dnext) ? act_sig(v.z) : 0.f;
                    o.w = (cb + 3 < dnext) ? act_sig(v.w) : 0.f;
                    *reinterpret_cast<float4*>(&ys[1 - p][w][bt][cb]) = o;
                }
            }
            __syncwarp();
            p ^= 1;
        }
    }
}

extern "C" void kernel_launch(void* const* d_in, const int* in_sizes, int n_in,
                              void* d_out, int out_size)
{
    const float* a0 = (const float*)d_in[0];
    const float* a1 = (const float*)d_in[1];
    // x: 1024*2*784 = 1,605,632 ; tensors: 10*784*64*2*64 = 64,225,280
    const float* x = a0;
    const float* t = a1;
    if (n_in >= 2 && in_sizes[0] > in_sizes[1]) { x = a1; t = a0; }

    const int nx = 2 * LEN * BTCH;
    xpose_kernel<<<(nx + 255) / 256, 256>>>(x);

    const int blocks = NCH * (BTCH / (NW * TB));   // 10 * 64 = 640 CTAs
    mps_main<<<blocks, NT>>>(t, (float*)d_out);
}